// round 11
// baseline (speedup 1.0000x reference)
#include <cuda_runtime.h>
#include <cstdint>

// POLLU RHS: dy[b][s] = sum_r S[s][r]*k[r]*C[a_r][b]*C[b_r][b]
// R6 structure with ONE reused smem buffer (20KB instead of 16+20=37KB):
//   phase 1: 16x 1KB TMA bulk loads fill buf[0..16KB) (mbarrier/expect_tx)
//   phase 2: warps copy their column to registers, compute derivatives
//   phase 3: __syncthreads (all reads done), restage buf as [TILE][20] output
//   phase 4: per-warp 2.5KB cp.async.bulk stores (proven optimal store path;
//            direct STG.128 was 5x L2-wavefront-amplified and regressed)
// 20KB/CTA lifts residency from 6 to the warp-slot limit of 8 CTAs/SM.

#define TILE 256
#define NSP  16    // species used as reactants (7,11,14,17 never read)

__device__ __forceinline__ uint32_t s2u(const void* p) {
    uint32_t a;
    asm("{ .reg .u64 t; cvta.to.shared.u64 t, %1; cvt.u32.u64 %0, t; }"
        : "=r"(a) : "l"(p));
    return a;
}

__constant__ int c_sp[NSP] = {0,1,2,3,4,5,6,8,9,10,12,13,15,16,18,19};

__global__ __launch_bounds__(TILE)
void pollu_kernel(const float* __restrict__ conc,
                  const float* __restrict__ k,
                  float* __restrict__ out,
                  int B)
{
    // One buffer, two lives: [NSP][TILE] input tile, then [TILE][20] output tile.
    __shared__ __align__(16) float s_buf[TILE * 20];   // 20 KB (>= NSP*TILE = 16 KB)
    __shared__ __align__(8)  uint64_t mbar;

    const int tid  = threadIdx.x;
    const int wid  = tid >> 5;
    const int lane = tid & 31;
    const int b0   = blockIdx.x * TILE;
    const int b    = b0 + tid;
    const int n_valid = min(TILE, B - b0);

    // Bulk path needs 16B-aligned addresses+sizes (uniform per block).
    const bool use_tma = ((B & 3) == 0) && ((n_valid & 3) == 0);

    float C0, C1, C2, C3, C4, C5, C6, C8, C9, C10, C12, C13, C15, C16, C18, C19;

    if (use_tma) {
        if (tid == 0) {
            asm volatile("mbarrier.init.shared.b64 [%0], 1;"
                         :: "r"(s2u(&mbar)) : "memory");
        }
        __syncthreads();   // publish mbarrier init before waits / TMA arrivals

        if (tid == 0) {
            const unsigned row_bytes = (unsigned)(n_valid * 4);
            asm volatile("mbarrier.arrive.expect_tx.shared.b64 _, [%0], %1;"
                         :: "r"(s2u(&mbar)), "r"(row_bytes * NSP) : "memory");
            #pragma unroll
            for (int i = 0; i < NSP; i++) {
                const float* gsrc = conc + (long long)c_sp[i] * B + b0;
                asm volatile(
                    "cp.async.bulk.shared::cta.global.mbarrier::complete_tx::bytes "
                    "[%0], [%1], %2, [%3];"
                    :: "r"(s2u(&s_buf[i * TILE])), "l"(gsrc),
                       "r"(row_bytes), "r"(s2u(&mbar))
                    : "memory");
            }
        }

        // sleep-wait for the whole 16KB tile (phase parity 0)
        {
            uint32_t mb = s2u(&mbar);
            asm volatile(
                "{\n\t.reg .pred P;\n\t"
                "WAIT_%=:\n\t"
                "mbarrier.try_wait.parity.acquire.cta.shared::cta.b64 P, [%0], 0, 0x989680;\n\t"
                "@P bra.uni DONE_%=;\n\t"
                "bra.uni WAIT_%=;\n\t"
                "DONE_%=:\n\t}"
                :: "r"(mb) : "memory");
        }

        // conflict-free LDS: consecutive lanes read consecutive words
        C0  = s_buf[ 0*TILE + tid];  C1  = s_buf[ 1*TILE + tid];
        C2  = s_buf[ 2*TILE + tid];  C3  = s_buf[ 3*TILE + tid];
        C4  = s_buf[ 4*TILE + tid];  C5  = s_buf[ 5*TILE + tid];
        C6  = s_buf[ 6*TILE + tid];  C8  = s_buf[ 7*TILE + tid];
        C9  = s_buf[ 8*TILE + tid];  C10 = s_buf[ 9*TILE + tid];
        C12 = s_buf[10*TILE + tid];  C13 = s_buf[11*TILE + tid];
        C15 = s_buf[12*TILE + tid];  C16 = s_buf[13*TILE + tid];
        C18 = s_buf[14*TILE + tid];  C19 = s_buf[15*TILE + tid];
    } else {
        // fallback (tail/misaligned): direct coalesced LDG
        if (b < B) {
            C0  = __ldg(&conc[ 0*B + b]);  C1  = __ldg(&conc[ 1*B + b]);
            C2  = __ldg(&conc[ 2*B + b]);  C3  = __ldg(&conc[ 3*B + b]);
            C4  = __ldg(&conc[ 4*B + b]);  C5  = __ldg(&conc[ 5*B + b]);
            C6  = __ldg(&conc[ 6*B + b]);  C8  = __ldg(&conc[ 8*B + b]);
            C9  = __ldg(&conc[ 9*B + b]);  C10 = __ldg(&conc[10*B + b]);
            C12 = __ldg(&conc[12*B + b]);  C13 = __ldg(&conc[13*B + b]);
            C15 = __ldg(&conc[15*B + b]);  C16 = __ldg(&conc[16*B + b]);
            C18 = __ldg(&conc[18*B + b]);  C19 = __ldg(&conc[19*B + b]);
        }
    }

    float d0=0,d1=0,d2=0,d3=0,d4=0,d5=0,d6=0,d7=0,d8=0,d9=0;
    float d10=0,d11=0,d12=0,d13=0,d14=0,d15=0,d16=0,d17=0,d18=0,d19=0;

    if (b < B) {
        // ---- 25 fluxes (k loads broadcast, L1-resident) ----
        float r1  = __ldg(&k[ 0]) * C0;
        float r2  = __ldg(&k[ 1]) * C1  * C3;
        float r3  = __ldg(&k[ 2]) * C4  * C1;
        float r4  = __ldg(&k[ 3]) * C6;
        float r5  = __ldg(&k[ 4]) * C6;
        float r6  = __ldg(&k[ 5]) * C6  * C5;
        float r7  = __ldg(&k[ 6]) * C8;
        float r8  = __ldg(&k[ 7]) * C8  * C5;
        float r9  = __ldg(&k[ 8]) * C10 * C1;
        float r10 = __ldg(&k[ 9]) * C10 * C0;
        float r11 = __ldg(&k[10]) * C12;
        float r12 = __ldg(&k[11]) * C9  * C1;
        float r13 = __ldg(&k[12]) * C13;
        float r14 = __ldg(&k[13]) * C0  * C5;
        float r15 = __ldg(&k[14]) * C2;
        float r16 = __ldg(&k[15]) * C3;
        float r17 = __ldg(&k[16]) * C3;
        float r18 = __ldg(&k[17]) * C15;
        float r19 = __ldg(&k[18]) * C15;
        float r20 = __ldg(&k[19]) * C16 * C5;
        float r21 = __ldg(&k[20]) * C18;
        float r22 = __ldg(&k[21]) * C18;
        float r23 = __ldg(&k[22]) * C0  * C3;
        float r24 = __ldg(&k[23]) * C18 * C0;
        float r25 = __ldg(&k[24]) * C19;

        // ---- stoichiometry ----
        d0  = -r1 - r10 - r14 - r23 - r24 + r2 + r3 + r9 + r11 + r12 + r22 + r25;
        d1  = -r2 - r3 - r9 - r12 + r1 + r21;
        d2  = -r15 + r1 + r17 + r19 + r22;
        d3  = -r2 - r16 - r17 - r23 + r15;
        d4  = -r3 + 2.0f*r4 + r6 + r7 + r13 + r20;
        d5  = -r6 - r8 - r14 - r20 + r3 + 2.0f*r18;
        d6  = -r4 - r5 - r6 + r13;
        d7  =  r4 + r5 + r6 + r7;
        d8  = -r7 - r8;
        d9  = -r12 + r7 + r9;
        d10 = -r9 - r10 + r8 + r11;
        d11 =  r9;
        d12 = -r11 + r10;
        d13 = -r13 + r12;
        d14 =  r14;
        d15 = -r18 - r19 + r16;
        d16 = -r20;
        d17 =  r20;
        d18 = -r21 - r22 - r24 + r23 + r25;
        d19 = -r25 + r24;
    }

    // ---- buffer life swap: all warps must finish reading inputs ----
    __syncthreads();

    if (b < B) {
        // 5x STS.128, conflict-free in unpadded [TILE][20] layout
        float4* srow = reinterpret_cast<float4*>(&s_buf[tid * 20]);
        srow[0] = make_float4(d0,  d1,  d2,  d3);
        srow[1] = make_float4(d4,  d5,  d6,  d7);
        srow[2] = make_float4(d8,  d9,  d10, d11);
        srow[3] = make_float4(d12, d13, d14, d15);
        srow[4] = make_float4(d16, d17, d18, d19);
    }

    // ---- per-warp drain ----
    const int warp_b0    = b0 + wid * 32;
    const int warp_valid = min(32, B - warp_b0);
    __syncwarp();
    if (warp_valid > 0) {
        asm volatile("fence.proxy.async.shared::cta;" ::: "memory");
        if (lane == 0) {
            float*   gdst  = out + (long long)warp_b0 * 20;               // 2560B-aligned
            unsigned bytes = (unsigned)(warp_valid * 20 * sizeof(float)); // mult of 16

            asm volatile(
                "cp.async.bulk.global.shared::cta.bulk_group [%0], [%1], %2;"
                :: "l"(gdst), "r"(s2u(&s_buf[wid * 32 * 20])), "r"(bytes)
                : "memory");
            asm volatile("cp.async.bulk.commit_group;" ::: "memory");
            asm volatile("cp.async.bulk.wait_group 0;" ::: "memory");
        }
    }
}

extern "C" void kernel_launch(void* const* d_in, const int* in_sizes, int n_in,
                              void* d_out, int out_size)
{
    // inputs per metadata order: t [1], conc_in [20*B], k [25]
    const float* conc = (const float*)d_in[1];
    const float* k    = (const float*)d_in[2];
    float* out        = (float*)d_out;
    const int B = in_sizes[1] / 20;

    const int grid = (B + TILE - 1) / TILE;
    pollu_kernel<<<grid, TILE>>>(conc, k, out, B);
}

// round 12
// speedup vs baseline: 1.4306x; 1.4306x over previous
#include <cuda_runtime.h>
#include <cstdint>

// POLLU RHS: dy[b][s] = sum_r S[s][r]*k[r]*C[a_r][b]*C[b_r][b]
// R6 structure (best-measured frontier) + one surgical fix:
//   Input : 16 used species rows per 256-col tile via 16x 1KB cp.async.bulk
//           (TMA) into s_in, one mbarrier/expect_tx, sleep-wait.
//   Output: unpadded [TILE][20] smem staging (conflict-free 5x STS.128),
//           per-warp 2.5KB cp.async.bulk stores.
//   FIX   : tail wait is cp.async.bulk.wait_group.READ 0 (CUTLASS
//           tma_store_wait pattern) — only waits until TMA has read smem,
//           NOT until the global write completes. Store finishes in the
//           background after CTA exit; per-warp tail shrinks by the full
//           L2/DRAM write round trip (~600+ cyc), improving SM turnover.

#define TILE 256
#define NSP  16    // species used as reactants (7,11,14,17 never read)

__device__ __forceinline__ uint32_t s2u(const void* p) {
    uint32_t a;
    asm("{ .reg .u64 t; cvta.to.shared.u64 t, %1; cvt.u32.u64 %0, t; }"
        : "=r"(a) : "l"(p));
    return a;
}

__constant__ int c_sp[NSP] = {0,1,2,3,4,5,6,8,9,10,12,13,15,16,18,19};

__global__ __launch_bounds__(TILE)
void pollu_kernel(const float* __restrict__ conc,
                  const float* __restrict__ k,
                  float* __restrict__ out,
                  int B)
{
    __shared__ __align__(16) float s_in[NSP * TILE];   // 16 KB
    __shared__ __align__(16) float s_out[TILE * 20];   // 20 KB
    __shared__ __align__(8)  uint64_t mbar;

    const int tid  = threadIdx.x;
    const int wid  = tid >> 5;
    const int lane = tid & 31;
    const int b0   = blockIdx.x * TILE;
    const int b    = b0 + tid;
    const int n_valid = min(TILE, B - b0);

    // Bulk path needs 16B-aligned addresses+sizes (uniform per block).
    const bool use_tma = ((B & 3) == 0) && ((n_valid & 3) == 0);

    float C0, C1, C2, C3, C4, C5, C6, C8, C9, C10, C12, C13, C15, C16, C18, C19;

    if (use_tma) {
        if (tid == 0) {
            asm volatile("mbarrier.init.shared.b64 [%0], 1;"
                         :: "r"(s2u(&mbar)) : "memory");
        }
        __syncthreads();   // publish mbarrier init before waits / TMA arrivals

        if (tid == 0) {
            const unsigned row_bytes = (unsigned)(n_valid * 4);
            asm volatile("mbarrier.arrive.expect_tx.shared.b64 _, [%0], %1;"
                         :: "r"(s2u(&mbar)), "r"(row_bytes * NSP) : "memory");
            #pragma unroll
            for (int i = 0; i < NSP; i++) {
                const float* gsrc = conc + (long long)c_sp[i] * B + b0;
                asm volatile(
                    "cp.async.bulk.shared::cta.global.mbarrier::complete_tx::bytes "
                    "[%0], [%1], %2, [%3];"
                    :: "r"(s2u(&s_in[i * TILE])), "l"(gsrc),
                       "r"(row_bytes), "r"(s2u(&mbar))
                    : "memory");
            }
        }

        // sleep-wait for the whole 16KB tile (phase parity 0)
        {
            uint32_t mb = s2u(&mbar);
            asm volatile(
                "{\n\t.reg .pred P;\n\t"
                "WAIT_%=:\n\t"
                "mbarrier.try_wait.parity.acquire.cta.shared::cta.b64 P, [%0], 0, 0x989680;\n\t"
                "@P bra.uni DONE_%=;\n\t"
                "bra.uni WAIT_%=;\n\t"
                "DONE_%=:\n\t}"
                :: "r"(mb) : "memory");
        }

        // conflict-free LDS: consecutive lanes read consecutive words
        C0  = s_in[ 0*TILE + tid];  C1  = s_in[ 1*TILE + tid];
        C2  = s_in[ 2*TILE + tid];  C3  = s_in[ 3*TILE + tid];
        C4  = s_in[ 4*TILE + tid];  C5  = s_in[ 5*TILE + tid];
        C6  = s_in[ 6*TILE + tid];  C8  = s_in[ 7*TILE + tid];
        C9  = s_in[ 8*TILE + tid];  C10 = s_in[ 9*TILE + tid];
        C12 = s_in[10*TILE + tid];  C13 = s_in[11*TILE + tid];
        C15 = s_in[12*TILE + tid];  C16 = s_in[13*TILE + tid];
        C18 = s_in[14*TILE + tid];  C19 = s_in[15*TILE + tid];
    } else {
        // fallback (tail/misaligned): direct coalesced LDG
        if (b < B) {
            C0  = __ldg(&conc[ 0*B + b]);  C1  = __ldg(&conc[ 1*B + b]);
            C2  = __ldg(&conc[ 2*B + b]);  C3  = __ldg(&conc[ 3*B + b]);
            C4  = __ldg(&conc[ 4*B + b]);  C5  = __ldg(&conc[ 5*B + b]);
            C6  = __ldg(&conc[ 6*B + b]);  C8  = __ldg(&conc[ 8*B + b]);
            C9  = __ldg(&conc[ 9*B + b]);  C10 = __ldg(&conc[10*B + b]);
            C12 = __ldg(&conc[12*B + b]);  C13 = __ldg(&conc[13*B + b]);
            C15 = __ldg(&conc[15*B + b]);  C16 = __ldg(&conc[16*B + b]);
            C18 = __ldg(&conc[18*B + b]);  C19 = __ldg(&conc[19*B + b]);
        }
    }

    if (b < B) {
        // ---- 25 fluxes (k loads broadcast, L1-resident) ----
        float r1  = __ldg(&k[ 0]) * C0;
        float r2  = __ldg(&k[ 1]) * C1  * C3;
        float r3  = __ldg(&k[ 2]) * C4  * C1;
        float r4  = __ldg(&k[ 3]) * C6;
        float r5  = __ldg(&k[ 4]) * C6;
        float r6  = __ldg(&k[ 5]) * C6  * C5;
        float r7  = __ldg(&k[ 6]) * C8;
        float r8  = __ldg(&k[ 7]) * C8  * C5;
        float r9  = __ldg(&k[ 8]) * C10 * C1;
        float r10 = __ldg(&k[ 9]) * C10 * C0;
        float r11 = __ldg(&k[10]) * C12;
        float r12 = __ldg(&k[11]) * C9  * C1;
        float r13 = __ldg(&k[12]) * C13;
        float r14 = __ldg(&k[13]) * C0  * C5;
        float r15 = __ldg(&k[14]) * C2;
        float r16 = __ldg(&k[15]) * C3;
        float r17 = __ldg(&k[16]) * C3;
        float r18 = __ldg(&k[17]) * C15;
        float r19 = __ldg(&k[18]) * C15;
        float r20 = __ldg(&k[19]) * C16 * C5;
        float r21 = __ldg(&k[20]) * C18;
        float r22 = __ldg(&k[21]) * C18;
        float r23 = __ldg(&k[22]) * C0  * C3;
        float r24 = __ldg(&k[23]) * C18 * C0;
        float r25 = __ldg(&k[24]) * C19;

        // ---- stoichiometry ----
        float d0  = -r1 - r10 - r14 - r23 - r24 + r2 + r3 + r9 + r11 + r12 + r22 + r25;
        float d1  = -r2 - r3 - r9 - r12 + r1 + r21;
        float d2  = -r15 + r1 + r17 + r19 + r22;
        float d3  = -r2 - r16 - r17 - r23 + r15;
        float d4  = -r3 + 2.0f*r4 + r6 + r7 + r13 + r20;
        float d5  = -r6 - r8 - r14 - r20 + r3 + 2.0f*r18;
        float d6  = -r4 - r5 - r6 + r13;
        float d7  =  r4 + r5 + r6 + r7;
        float d8  = -r7 - r8;
        float d9  = -r12 + r7 + r9;
        float d10 = -r9 - r10 + r8 + r11;
        float d11 =  r9;
        float d12 = -r11 + r10;
        float d13 = -r13 + r12;
        float d14 =  r14;
        float d15 = -r18 - r19 + r16;
        float d16 = -r20;
        float d17 =  r20;
        float d18 = -r21 - r22 - r24 + r23 + r25;
        float d19 = -r25 + r24;

        // ---- 5x STS.128, conflict-free in unpadded [TILE][20] layout ----
        float4* srow = reinterpret_cast<float4*>(&s_out[tid * 20]);
        srow[0] = make_float4(d0,  d1,  d2,  d3);
        srow[1] = make_float4(d4,  d5,  d6,  d7);
        srow[2] = make_float4(d8,  d9,  d10, d11);
        srow[3] = make_float4(d12, d13, d14, d15);
        srow[4] = make_float4(d16, d17, d18, d19);
    }

    // ---- per-warp drain (no block barriers) ----
    const int warp_b0    = b0 + wid * 32;
    const int warp_valid = min(32, B - warp_b0);
    __syncwarp();
    if (warp_valid > 0) {
        asm volatile("fence.proxy.async.shared::cta;" ::: "memory");
        if (lane == 0) {
            float*   gdst  = out + (long long)warp_b0 * 20;               // 2560B-aligned
            unsigned bytes = (unsigned)(warp_valid * 20 * sizeof(float)); // mult of 16

            asm volatile(
                "cp.async.bulk.global.shared::cta.bulk_group [%0], [%1], %2;"
                :: "l"(gdst), "r"(s2u(&s_out[wid * 32 * 20])), "r"(bytes)
                : "memory");
            asm volatile("cp.async.bulk.commit_group;" ::: "memory");
            // Wait only until TMA has READ the smem source (safe for CTA
            // exit / smem dealloc); the global write completes in background.
            asm volatile("cp.async.bulk.wait_group.read 0;" ::: "memory");
        }
    }
}

extern "C" void kernel_launch(void* const* d_in, const int* in_sizes, int n_in,
                              void* d_out, int out_size)
{
    // inputs per metadata order: t [1], conc_in [20*B], k [25]
    const float* conc = (const float*)d_in[1];
    const float* k    = (const float*)d_in[2];
    float* out        = (float*)d_out;
    const int B = in_sizes[1] / 20;

    const int grid = (B + TILE - 1) / TILE;
    pollu_kernel<<<grid, TILE>>>(conc, k, out, B);
}

// round 13
// speedup vs baseline: 1.4342x; 1.0025x over previous
#include <cuda_runtime.h>
#include <cstdint>

// POLLU RHS: dy[b][s] = sum_r S[s][r]*k[r]*C[a_r][b]*C[b_r][b]
// Converged structure (R12) + prologue micro-opts:
//   Input : 16 used species rows per 256-col tile via 16x 1KB cp.async.bulk
//           into s_in; TMA issue SPLIT across two issuer threads (tid 0:
//           rows 0-7, tid 32: rows 8-15) to halve the serial issue chain.
//           expect_tx posted by tid 0 BEFORE the barrier; copies issued after.
//   k     : staged once per block into smem by warp 0 (covered by the same
//           barrier); per-thread k reads become LDS broadcasts instead of
//           25 LDG wavefronts per thread.
//   Output: unpadded [TILE][20] smem staging (conflict-free 5x STS.128),
//           per-warp 2.5KB cp.async.bulk stores, tail = wait_group.READ 0
//           (waits only for TMA's smem read; global write drains after exit).

#define TILE 256
#define NSP  16    // species used as reactants (7,11,14,17 never read)

__device__ __forceinline__ uint32_t s2u(const void* p) {
    uint32_t a;
    asm("{ .reg .u64 t; cvta.to.shared.u64 t, %1; cvt.u32.u64 %0, t; }"
        : "=r"(a) : "l"(p));
    return a;
}

__constant__ int c_sp[NSP] = {0,1,2,3,4,5,6,8,9,10,12,13,15,16,18,19};

__global__ __launch_bounds__(TILE)
void pollu_kernel(const float* __restrict__ conc,
                  const float* __restrict__ k,
                  float* __restrict__ out,
                  int B)
{
    __shared__ __align__(16) float s_in[NSP * TILE];   // 16 KB
    __shared__ __align__(16) float s_out[TILE * 20];   // 20 KB
    __shared__ float s_k[25];
    __shared__ __align__(8) uint64_t mbar;

    const int tid  = threadIdx.x;
    const int wid  = tid >> 5;
    const int lane = tid & 31;
    const int b0   = blockIdx.x * TILE;
    const int b    = b0 + tid;
    const int n_valid = min(TILE, B - b0);

    // Bulk path needs 16B-aligned addresses+sizes (uniform per block).
    const bool use_tma = ((B & 3) == 0) && ((n_valid & 3) == 0);

    // ---- prologue: k -> smem (warp 0), mbarrier init + expect_tx (tid 0) ----
    if (tid < 25) s_k[tid] = __ldg(&k[tid]);
    if (use_tma && tid == 0) {
        asm volatile("mbarrier.init.shared.b64 [%0], 1;"
                     :: "r"(s2u(&mbar)) : "memory");
        const unsigned total = (unsigned)(n_valid * 4) * NSP;
        asm volatile("mbarrier.arrive.expect_tx.shared.b64 _, [%0], %1;"
                     :: "r"(s2u(&mbar)), "r"(total) : "memory");
    }
    __syncthreads();   // publish mbarrier init/expect + s_k before use

    float C0, C1, C2, C3, C4, C5, C6, C8, C9, C10, C12, C13, C15, C16, C18, C19;

    if (use_tma) {
        // split issue: tid 0 -> rows 0..7, tid 32 -> rows 8..15
        if (tid == 0 || tid == 32) {
            const unsigned row_bytes = (unsigned)(n_valid * 4);
            const int base = (tid == 0) ? 0 : 8;
            #pragma unroll
            for (int i = 0; i < NSP / 2; i++) {
                const int r = base + i;
                const float* gsrc = conc + (long long)c_sp[r] * B + b0;
                asm volatile(
                    "cp.async.bulk.shared::cta.global.mbarrier::complete_tx::bytes "
                    "[%0], [%1], %2, [%3];"
                    :: "r"(s2u(&s_in[r * TILE])), "l"(gsrc),
                       "r"(row_bytes), "r"(s2u(&mbar))
                    : "memory");
            }
        }

        // sleep-wait for the whole 16KB tile (phase parity 0)
        {
            uint32_t mb = s2u(&mbar);
            asm volatile(
                "{\n\t.reg .pred P;\n\t"
                "WAIT_%=:\n\t"
                "mbarrier.try_wait.parity.acquire.cta.shared::cta.b64 P, [%0], 0, 0x989680;\n\t"
                "@P bra.uni DONE_%=;\n\t"
                "bra.uni WAIT_%=;\n\t"
                "DONE_%=:\n\t}"
                :: "r"(mb) : "memory");
        }

        // conflict-free LDS: consecutive lanes read consecutive words
        C0  = s_in[ 0*TILE + tid];  C1  = s_in[ 1*TILE + tid];
        C2  = s_in[ 2*TILE + tid];  C3  = s_in[ 3*TILE + tid];
        C4  = s_in[ 4*TILE + tid];  C5  = s_in[ 5*TILE + tid];
        C6  = s_in[ 6*TILE + tid];  C8  = s_in[ 7*TILE + tid];
        C9  = s_in[ 8*TILE + tid];  C10 = s_in[ 9*TILE + tid];
        C12 = s_in[10*TILE + tid];  C13 = s_in[11*TILE + tid];
        C15 = s_in[12*TILE + tid];  C16 = s_in[13*TILE + tid];
        C18 = s_in[14*TILE + tid];  C19 = s_in[15*TILE + tid];
    } else {
        // fallback (tail/misaligned): direct coalesced LDG
        if (b < B) {
            C0  = __ldg(&conc[ 0*B + b]);  C1  = __ldg(&conc[ 1*B + b]);
            C2  = __ldg(&conc[ 2*B + b]);  C3  = __ldg(&conc[ 3*B + b]);
            C4  = __ldg(&conc[ 4*B + b]);  C5  = __ldg(&conc[ 5*B + b]);
            C6  = __ldg(&conc[ 6*B + b]);  C8  = __ldg(&conc[ 8*B + b]);
            C9  = __ldg(&conc[ 9*B + b]);  C10 = __ldg(&conc[10*B + b]);
            C12 = __ldg(&conc[12*B + b]);  C13 = __ldg(&conc[13*B + b]);
            C15 = __ldg(&conc[15*B + b]);  C16 = __ldg(&conc[16*B + b]);
            C18 = __ldg(&conc[18*B + b]);  C19 = __ldg(&conc[19*B + b]);
        }
    }

    if (b < B) {
        // ---- 25 fluxes (k from smem: broadcast LDS, no bank conflicts) ----
        float r1  = s_k[ 0] * C0;
        float r2  = s_k[ 1] * C1  * C3;
        float r3  = s_k[ 2] * C4  * C1;
        float r4  = s_k[ 3] * C6;
        float r5  = s_k[ 4] * C6;
        float r6  = s_k[ 5] * C6  * C5;
        float r7  = s_k[ 6] * C8;
        float r8  = s_k[ 7] * C8  * C5;
        float r9  = s_k[ 8] * C10 * C1;
        float r10 = s_k[ 9] * C10 * C0;
        float r11 = s_k[10] * C12;
        float r12 = s_k[11] * C9  * C1;
        float r13 = s_k[12] * C13;
        float r14 = s_k[13] * C0  * C5;
        float r15 = s_k[14] * C2;
        float r16 = s_k[15] * C3;
        float r17 = s_k[16] * C3;
        float r18 = s_k[17] * C15;
        float r19 = s_k[18] * C15;
        float r20 = s_k[19] * C16 * C5;
        float r21 = s_k[20] * C18;
        float r22 = s_k[21] * C18;
        float r23 = s_k[22] * C0  * C3;
        float r24 = s_k[23] * C18 * C0;
        float r25 = s_k[24] * C19;

        // ---- stoichiometry ----
        float d0  = -r1 - r10 - r14 - r23 - r24 + r2 + r3 + r9 + r11 + r12 + r22 + r25;
        float d1  = -r2 - r3 - r9 - r12 + r1 + r21;
        float d2  = -r15 + r1 + r17 + r19 + r22;
        float d3  = -r2 - r16 - r17 - r23 + r15;
        float d4  = -r3 + 2.0f*r4 + r6 + r7 + r13 + r20;
        float d5  = -r6 - r8 - r14 - r20 + r3 + 2.0f*r18;
        float d6  = -r4 - r5 - r6 + r13;
        float d7  =  r4 + r5 + r6 + r7;
        float d8  = -r7 - r8;
        float d9  = -r12 + r7 + r9;
        float d10 = -r9 - r10 + r8 + r11;
        float d11 =  r9;
        float d12 = -r11 + r10;
        float d13 = -r13 + r12;
        float d14 =  r14;
        float d15 = -r18 - r19 + r16;
        float d16 = -r20;
        float d17 =  r20;
        float d18 = -r21 - r22 - r24 + r23 + r25;
        float d19 = -r25 + r24;

        // ---- 5x STS.128, conflict-free in unpadded [TILE][20] layout ----
        float4* srow = reinterpret_cast<float4*>(&s_out[tid * 20]);
        srow[0] = make_float4(d0,  d1,  d2,  d3);
        srow[1] = make_float4(d4,  d5,  d6,  d7);
        srow[2] = make_float4(d8,  d9,  d10, d11);
        srow[3] = make_float4(d12, d13, d14, d15);
        srow[4] = make_float4(d16, d17, d18, d19);
    }

    // ---- per-warp drain (no block barriers) ----
    const int warp_b0    = b0 + wid * 32;
    const int warp_valid = min(32, B - warp_b0);
    __syncwarp();
    if (warp_valid > 0) {
        asm volatile("fence.proxy.async.shared::cta;" ::: "memory");
        if (lane == 0) {
            float*   gdst  = out + (long long)warp_b0 * 20;               // 2560B-aligned
            unsigned bytes = (unsigned)(warp_valid * 20 * sizeof(float)); // mult of 16

            asm volatile(
                "cp.async.bulk.global.shared::cta.bulk_group [%0], [%1], %2;"
                :: "l"(gdst), "r"(s2u(&s_out[wid * 32 * 20])), "r"(bytes)
                : "memory");
            asm volatile("cp.async.bulk.commit_group;" ::: "memory");
            // Wait only until TMA has READ the smem source (safe for smem
            // dealloc at CTA exit); global write completes in background.
            asm volatile("cp.async.bulk.wait_group.read 0;" ::: "memory");
        }
    }
}

extern "C" void kernel_launch(void* const* d_in, const int* in_sizes, int n_in,
                              void* d_out, int out_size)
{
    // inputs per metadata order: t [1], conc_in [20*B], k [25]
    const float* conc = (const float*)d_in[1];
    const float* k    = (const float*)d_in[2];
    float* out        = (float*)d_out;
    const int B = in_sizes[1] / 20;

    const int grid = (B + TILE - 1) / TILE;
    pollu_kernel<<<grid, TILE>>>(conc, k, out, B);
}

// round 14
// speedup vs baseline: 1.4823x; 1.0335x over previous
#include <cuda_runtime.h>
#include <cstdint>

// POLLU RHS: dy[b][s] = sum_r S[s][r]*k[r]*C[a_r][b]*C[b_r][b]
// Converged structure (R13) + register/occupancy reclaim:
//   * __launch_bounds__(256, 6): 6 CTAs/SM is the smem ceiling (37KB each);
//     cap regs (~42) so residency isn't silently reduced below it (R13 hit
//     48 regs / 55.7% occ after the prologue micro-opts).
//   * TMA issue loop uses compile-time species offsets (no const-mem LDC /
//     IMAD chain in the serial issuer path).
//   Input : 16 used species rows per 256-col tile via 16x 1KB cp.async.bulk,
//           issue split across tid 0 (rows 0-7) and tid 32 (rows 8-15),
//           one mbarrier + expect_tx posted before the barrier.
//   k     : staged to smem once per block (LDS broadcast thereafter).
//   Output: unpadded [TILE][20] smem staging (conflict-free 5x STS.128),
//           per-warp 2.5KB cp.async.bulk stores, tail = wait_group.READ 0.

#define TILE 256
#define NSP  16    // species used as reactants (7,11,14,17 never read)

__device__ __forceinline__ uint32_t s2u(const void* p) {
    uint32_t a;
    asm("{ .reg .u64 t; cvta.to.shared.u64 t, %1; cvt.u32.u64 %0, t; }"
        : "=r"(a) : "l"(p));
    return a;
}

__device__ __forceinline__ void bulk_load_row(uint32_t sdst, const float* gsrc,
                                              unsigned bytes, uint32_t mb)
{
    asm volatile(
        "cp.async.bulk.shared::cta.global.mbarrier::complete_tx::bytes "
        "[%0], [%1], %2, [%3];"
        :: "r"(sdst), "l"(gsrc), "r"(bytes), "r"(mb)
        : "memory");
}

__global__ __launch_bounds__(TILE, 6)
void pollu_kernel(const float* __restrict__ conc,
                  const float* __restrict__ k,
                  float* __restrict__ out,
                  int B)
{
    __shared__ __align__(16) float s_in[NSP * TILE];   // 16 KB
    __shared__ __align__(16) float s_out[TILE * 20];   // 20 KB
    __shared__ float s_k[25];
    __shared__ __align__(8) uint64_t mbar;

    const int tid  = threadIdx.x;
    const int wid  = tid >> 5;
    const int lane = tid & 31;
    const int b0   = blockIdx.x * TILE;
    const int b    = b0 + tid;
    const int n_valid = min(TILE, B - b0);

    // Bulk path needs 16B-aligned addresses+sizes (uniform per block).
    const bool use_tma = ((B & 3) == 0) && ((n_valid & 3) == 0);

    // ---- prologue: k -> smem, mbarrier init + expect_tx ----
    if (tid < 25) s_k[tid] = __ldg(&k[tid]);
    if (use_tma && tid == 0) {
        asm volatile("mbarrier.init.shared.b64 [%0], 1;"
                     :: "r"(s2u(&mbar)) : "memory");
        const unsigned total = (unsigned)(n_valid * 4) * NSP;
        asm volatile("mbarrier.arrive.expect_tx.shared.b64 _, [%0], %1;"
                     :: "r"(s2u(&mbar)), "r"(total) : "memory");
    }
    __syncthreads();   // publish mbarrier init/expect + s_k

    float C0, C1, C2, C3, C4, C5, C6, C8, C9, C10, C12, C13, C15, C16, C18, C19;

    if (use_tma) {
        // split issue, species offsets as compile-time literals
        const unsigned rb = (unsigned)(n_valid * 4);
        const uint32_t mb = s2u(&mbar);
        const long long LB = (long long)B;
        if (tid == 0) {
            bulk_load_row(s2u(&s_in[ 0*TILE]), conc +  0*LB + b0, rb, mb);
            bulk_load_row(s2u(&s_in[ 1*TILE]), conc +  1*LB + b0, rb, mb);
            bulk_load_row(s2u(&s_in[ 2*TILE]), conc +  2*LB + b0, rb, mb);
            bulk_load_row(s2u(&s_in[ 3*TILE]), conc +  3*LB + b0, rb, mb);
            bulk_load_row(s2u(&s_in[ 4*TILE]), conc +  4*LB + b0, rb, mb);
            bulk_load_row(s2u(&s_in[ 5*TILE]), conc +  5*LB + b0, rb, mb);
            bulk_load_row(s2u(&s_in[ 6*TILE]), conc +  6*LB + b0, rb, mb);
            bulk_load_row(s2u(&s_in[ 7*TILE]), conc +  8*LB + b0, rb, mb);
        } else if (tid == 32) {
            bulk_load_row(s2u(&s_in[ 8*TILE]), conc +  9*LB + b0, rb, mb);
            bulk_load_row(s2u(&s_in[ 9*TILE]), conc + 10*LB + b0, rb, mb);
            bulk_load_row(s2u(&s_in[10*TILE]), conc + 12*LB + b0, rb, mb);
            bulk_load_row(s2u(&s_in[11*TILE]), conc + 13*LB + b0, rb, mb);
            bulk_load_row(s2u(&s_in[12*TILE]), conc + 15*LB + b0, rb, mb);
            bulk_load_row(s2u(&s_in[13*TILE]), conc + 16*LB + b0, rb, mb);
            bulk_load_row(s2u(&s_in[14*TILE]), conc + 18*LB + b0, rb, mb);
            bulk_load_row(s2u(&s_in[15*TILE]), conc + 19*LB + b0, rb, mb);
        }

        // sleep-wait for the whole 16KB tile (phase parity 0)
        asm volatile(
            "{\n\t.reg .pred P;\n\t"
            "WAIT_%=:\n\t"
            "mbarrier.try_wait.parity.acquire.cta.shared::cta.b64 P, [%0], 0, 0x989680;\n\t"
            "@P bra.uni DONE_%=;\n\t"
            "bra.uni WAIT_%=;\n\t"
            "DONE_%=:\n\t}"
            :: "r"(mb) : "memory");

        // conflict-free LDS: consecutive lanes read consecutive words
        C0  = s_in[ 0*TILE + tid];  C1  = s_in[ 1*TILE + tid];
        C2  = s_in[ 2*TILE + tid];  C3  = s_in[ 3*TILE + tid];
        C4  = s_in[ 4*TILE + tid];  C5  = s_in[ 5*TILE + tid];
        C6  = s_in[ 6*TILE + tid];  C8  = s_in[ 7*TILE + tid];
        C9  = s_in[ 8*TILE + tid];  C10 = s_in[ 9*TILE + tid];
        C12 = s_in[10*TILE + tid];  C13 = s_in[11*TILE + tid];
        C15 = s_in[12*TILE + tid];  C16 = s_in[13*TILE + tid];
        C18 = s_in[14*TILE + tid];  C19 = s_in[15*TILE + tid];
    } else {
        // fallback (tail/misaligned): direct coalesced LDG
        if (b < B) {
            C0  = __ldg(&conc[ 0*B + b]);  C1  = __ldg(&conc[ 1*B + b]);
            C2  = __ldg(&conc[ 2*B + b]);  C3  = __ldg(&conc[ 3*B + b]);
            C4  = __ldg(&conc[ 4*B + b]);  C5  = __ldg(&conc[ 5*B + b]);
            C6  = __ldg(&conc[ 6*B + b]);  C8  = __ldg(&conc[ 8*B + b]);
            C9  = __ldg(&conc[ 9*B + b]);  C10 = __ldg(&conc[10*B + b]);
            C12 = __ldg(&conc[12*B + b]);  C13 = __ldg(&conc[13*B + b]);
            C15 = __ldg(&conc[15*B + b]);  C16 = __ldg(&conc[16*B + b]);
            C18 = __ldg(&conc[18*B + b]);  C19 = __ldg(&conc[19*B + b]);
        }
    }

    if (b < B) {
        // ---- 25 fluxes (k from smem: broadcast LDS) ----
        float r1  = s_k[ 0] * C0;
        float r2  = s_k[ 1] * C1  * C3;
        float r3  = s_k[ 2] * C4  * C1;
        float r4  = s_k[ 3] * C6;
        float r5  = s_k[ 4] * C6;
        float r6  = s_k[ 5] * C6  * C5;
        float r7  = s_k[ 6] * C8;
        float r8  = s_k[ 7] * C8  * C5;
        float r9  = s_k[ 8] * C10 * C1;
        float r10 = s_k[ 9] * C10 * C0;
        float r11 = s_k[10] * C12;
        float r12 = s_k[11] * C9  * C1;
        float r13 = s_k[12] * C13;
        float r14 = s_k[13] * C0  * C5;
        float r15 = s_k[14] * C2;
        float r16 = s_k[15] * C3;
        float r17 = s_k[16] * C3;
        float r18 = s_k[17] * C15;
        float r19 = s_k[18] * C15;
        float r20 = s_k[19] * C16 * C5;
        float r21 = s_k[20] * C18;
        float r22 = s_k[21] * C18;
        float r23 = s_k[22] * C0  * C3;
        float r24 = s_k[23] * C18 * C0;
        float r25 = s_k[24] * C19;

        // ---- stoichiometry ----
        float d0  = -r1 - r10 - r14 - r23 - r24 + r2 + r3 + r9 + r11 + r12 + r22 + r25;
        float d1  = -r2 - r3 - r9 - r12 + r1 + r21;
        float d2  = -r15 + r1 + r17 + r19 + r22;
        float d3  = -r2 - r16 - r17 - r23 + r15;
        float d4  = -r3 + 2.0f*r4 + r6 + r7 + r13 + r20;
        float d5  = -r6 - r8 - r14 - r20 + r3 + 2.0f*r18;
        float d6  = -r4 - r5 - r6 + r13;
        float d7  =  r4 + r5 + r6 + r7;
        float d8  = -r7 - r8;
        float d9  = -r12 + r7 + r9;
        float d10 = -r9 - r10 + r8 + r11;
        float d11 =  r9;
        float d12 = -r11 + r10;
        float d13 = -r13 + r12;
        float d14 =  r14;
        float d15 = -r18 - r19 + r16;
        float d16 = -r20;
        float d17 =  r20;
        float d18 = -r21 - r22 - r24 + r23 + r25;
        float d19 = -r25 + r24;

        // ---- 5x STS.128, conflict-free in unpadded [TILE][20] layout ----
        float4* srow = reinterpret_cast<float4*>(&s_out[tid * 20]);
        srow[0] = make_float4(d0,  d1,  d2,  d3);
        srow[1] = make_float4(d4,  d5,  d6,  d7);
        srow[2] = make_float4(d8,  d9,  d10, d11);
        srow[3] = make_float4(d12, d13, d14, d15);
        srow[4] = make_float4(d16, d17, d18, d19);
    }

    // ---- per-warp drain (no block barriers) ----
    const int warp_b0    = b0 + wid * 32;
    const int warp_valid = min(32, B - warp_b0);
    __syncwarp();
    if (warp_valid > 0) {
        asm volatile("fence.proxy.async.shared::cta;" ::: "memory");
        if (lane == 0) {
            float*   gdst  = out + (long long)warp_b0 * 20;               // 2560B-aligned
            unsigned bytes = (unsigned)(warp_valid * 20 * sizeof(float)); // mult of 16

            asm volatile(
                "cp.async.bulk.global.shared::cta.bulk_group [%0], [%1], %2;"
                :: "l"(gdst), "r"(s2u(&s_out[wid * 32 * 20])), "r"(bytes)
                : "memory");
            asm volatile("cp.async.bulk.commit_group;" ::: "memory");
            // Wait only until TMA has READ the smem source (safe for smem
            // dealloc at CTA exit); global write completes in background.
            asm volatile("cp.async.bulk.wait_group.read 0;" ::: "memory");
        }
    }
}

extern "C" void kernel_launch(void* const* d_in, const int* in_sizes, int n_in,
                              void* d_out, int out_size)
{
    // inputs per metadata order: t [1], conc_in [20*B], k [25]
    const float* conc = (const float*)d_in[1];
    const float* k    = (const float*)d_in[2];
    float* out        = (float*)d_out;
    const int B = in_sizes[1] / 20;

    const int grid = (B + TILE - 1) / TILE;
    pollu_kernel<<<grid, TILE>>>(conc, k, out, B);
}